// round 4
// baseline (speedup 1.0000x reference)
#include <cuda_runtime.h>
#include <stdint.h>

// ---------------------------------------------------------------------------
// TripletContrastiveLoss
//   features [B,D] f32, labels [B] int, domain [B] int  ->  scalar f32
//   f = normalize(features); d(i,j) over (herb i, field j) pairs;
//   per-anchor min pos / min neg distance; hinge margin 0.3; mean over valid.
// Strategy: compact anchors/fields, fp32 tiled GEMM of dots fused with
// masked min reduction (on d^2, monotonic), atomicMin on float bits.
// ---------------------------------------------------------------------------

#define BMAX 8192
#define DMAX 1024
#define INFBITS 0x7f800000u

#define BM 128
#define BN 128
#define BK 16
#define TM 8
#define TN 8
#define PAD 4   // smem row padding (keeps float4 alignment)

__device__ float g_A[(size_t)BMAX * DMAX];   // normalized anchor rows (compact)
__device__ float g_F[(size_t)BMAX * DMAX];   // normalized field rows  (compact)
__device__ int   g_aRow[BMAX];
__device__ int   g_fRow[BMAX];
__device__ int   g_aLab[BMAX];
__device__ int   g_fLab[BMAX];
__device__ int   g_aCnt;
__device__ int   g_fCnt;
__device__ unsigned g_posBits[BMAX];
__device__ unsigned g_negBits[BMAX];
__device__ int   g_is64;

// ---- K0: reset scalars --------------------------------------------------
__global__ void k0_reset() {
    g_aCnt = 0;
    g_fCnt = 0;
    g_is64 = 1;
}

// ---- K1: init min arrays + dtype detection ------------------------------
// If labels are int64 (values < 2^31), every odd 32-bit word is 0.
// If int32 (random 0..99), some odd word is nonzero with overwhelming prob.
__global__ void k1_init_detect(const unsigned* __restrict__ labw, int B) {
    int i = blockIdx.x * blockDim.x + threadIdx.x;
    if (i < B) {
        g_posBits[i] = INFBITS;
        g_negBits[i] = INFBITS;
        if ((i & 1) && labw[i] != 0u) g_is64 = 0;   // all writers write 0: no race
    }
}

// ---- K2: partition into compact anchor/field lists ----------------------
__global__ void k2_partition(const void* __restrict__ labels,
                             const void* __restrict__ doms, int B) {
    int i = blockIdx.x * blockDim.x + threadIdx.x;
    if (i >= B) return;
    int is64 = g_is64;
    long long dom, lab;
    if (is64) {
        dom = ((const long long*)doms)[i];
        lab = ((const long long*)labels)[i];
    } else {
        dom = ((const int*)doms)[i];
        lab = ((const int*)labels)[i];
    }
    if (dom == 0) {
        int p = atomicAdd(&g_aCnt, 1);
        g_aRow[p] = i;
        g_aLab[p] = (int)lab;
    } else if (dom == 1) {
        int p = atomicAdd(&g_fCnt, 1);
        g_fRow[p] = i;
        g_fLab[p] = (int)lab;
    }
}

// ---- K3: normalize + gather ---------------------------------------------
// grid (B, 2): y==0 anchors, y==1 fields. 256 threads per block.
__global__ void k3_normalize(const float* __restrict__ feat, int D) {
    int side = blockIdx.y;
    int n = side ? g_fCnt : g_aCnt;
    int b = blockIdx.x;
    if (b >= n) return;
    int row = side ? g_fRow[b] : g_aRow[b];
    const float4* src = (const float4*)(feat + (size_t)row * D);
    float4* dst = (float4*)((side ? g_F : g_A) + (size_t)b * D);
    int nv = D >> 2;
    int tid = threadIdx.x;

    float s = 0.f;
    for (int t = tid; t < nv; t += blockDim.x) {
        float4 v = src[t];
        s += v.x * v.x + v.y * v.y + v.z * v.z + v.w * v.w;
    }
    // block reduce
    __shared__ float red[8];
    #pragma unroll
    for (int o = 16; o; o >>= 1) s += __shfl_xor_sync(0xffffffffu, s, o);
    if ((tid & 31) == 0) red[tid >> 5] = s;
    __syncthreads();
    __shared__ float s_scale;
    if (tid == 0) {
        float t = 0.f;
        #pragma unroll
        for (int w = 0; w < 8; w++) t += red[w];
        s_scale = 1.f / fmaxf(sqrtf(t), 1e-12f);
    }
    __syncthreads();
    float scale = s_scale;
    for (int t = tid; t < nv; t += blockDim.x) {
        float4 v = src[t];
        v.x *= scale; v.y *= scale; v.z *= scale; v.w *= scale;
        dst[t] = v;
    }
}

// ---- K4: fused GEMM + masked min ----------------------------------------
__global__ void __launch_bounds__(256, 2)
k4_gemm_min(int D) {
    const int NA = g_aCnt;
    const int NF = g_fCnt;
    const int by = blockIdx.y, bx = blockIdx.x;
    if (by * BM >= NA || bx * BN >= NF) return;

    __shared__ float As[BK * (BM + PAD)];
    __shared__ float Bs[BK * (BN + PAD)];
    __shared__ int sAlab[BM];
    __shared__ int sFlab[BN];

    const int tid = threadIdx.x;
    const int tx = tid & 15;
    const int ty = tid >> 4;

    if (tid < BM) {
        int a = by * BM + tid;
        sAlab[tid] = (a < NA) ? g_aLab[a] : -1;
        int f = bx * BN + tid;
        sFlab[tid] = (f < NF) ? g_fLab[f] : -1;
    }

    float acc[TM][TN];
    #pragma unroll
    for (int i = 0; i < TM; i++)
        #pragma unroll
        for (int j = 0; j < TN; j++) acc[i][j] = 0.f;

    for (int k0 = 0; k0 < D; k0 += BK) {
        // cooperative load: 128 rows x 16 k = 512 float4 per matrix, 2 per thread
        #pragma unroll
        for (int l = 0; l < 2; l++) {
            int idx = tid + l * 256;         // 0..511
            int m  = idx >> 2;               // 0..127
            int kq = (idx & 3) << 2;         // 0,4,8,12
            float4 va = make_float4(0.f, 0.f, 0.f, 0.f);
            float4 vb = va;
            int ga = by * BM + m;
            int gf = bx * BN + m;
            if (ga < NA) va = *(const float4*)&g_A[(size_t)ga * D + k0 + kq];
            if (gf < NF) vb = *(const float4*)&g_F[(size_t)gf * D + k0 + kq];
            As[(kq + 0) * (BM + PAD) + m] = va.x;
            As[(kq + 1) * (BM + PAD) + m] = va.y;
            As[(kq + 2) * (BM + PAD) + m] = va.z;
            As[(kq + 3) * (BM + PAD) + m] = va.w;
            Bs[(kq + 0) * (BN + PAD) + m] = vb.x;
            Bs[(kq + 1) * (BN + PAD) + m] = vb.y;
            Bs[(kq + 2) * (BN + PAD) + m] = vb.z;
            Bs[(kq + 3) * (BN + PAD) + m] = vb.w;
        }
        __syncthreads();

        #pragma unroll
        for (int k = 0; k < BK; k++) {
            float4 a0 = *(const float4*)&As[k * (BM + PAD) + ty * TM];
            float4 a1 = *(const float4*)&As[k * (BM + PAD) + ty * TM + 4];
            float4 b0 = *(const float4*)&Bs[k * (BN + PAD) + tx * TN];
            float4 b1 = *(const float4*)&Bs[k * (BN + PAD) + tx * TN + 4];
            float af[TM] = {a0.x, a0.y, a0.z, a0.w, a1.x, a1.y, a1.z, a1.w};
            float bf[TN] = {b0.x, b0.y, b0.z, b0.w, b1.x, b1.y, b1.z, b1.w};
            #pragma unroll
            for (int i = 0; i < TM; i++)
                #pragma unroll
                for (int j = 0; j < TN; j++)
                    acc[i][j] = fmaf(af[i], bf[j], acc[i][j]);
        }
        __syncthreads();
    }

    // epilogue: d^2 = max(2 - 2*dot, 0); masked min per anchor row
    float posm[TM], negm[TM];
    #pragma unroll
    for (int i = 0; i < TM; i++) {
        posm[i] = __uint_as_float(INFBITS);
        negm[i] = __uint_as_float(INFBITS);
    }
    #pragma unroll
    for (int i = 0; i < TM; i++) {
        int al = sAlab[ty * TM + i];
        #pragma unroll
        for (int j = 0; j < TN; j++) {
            int fl = sFlab[tx * TN + j];
            float d2 = fmaxf(fmaf(-2.f, acc[i][j], 2.f), 0.f);
            if (fl >= 0) {
                if (fl == al) posm[i] = fminf(posm[i], d2);
                else          negm[i] = fminf(negm[i], d2);
            }
        }
    }
    // reduce mins across the 16 tx lanes (xor 1,2,4,8 stays within 16-lane half)
    #pragma unroll
    for (int o = 1; o < 16; o <<= 1) {
        #pragma unroll
        for (int i = 0; i < TM; i++) {
            posm[i] = fminf(posm[i], __shfl_xor_sync(0xffffffffu, posm[i], o));
            negm[i] = fminf(negm[i], __shfl_xor_sync(0xffffffffu, negm[i], o));
        }
    }
    if (tx == 0) {
        #pragma unroll
        for (int i = 0; i < TM; i++) {
            int a = by * BM + ty * TM + i;
            if (a < NA) {
                atomicMin(&g_posBits[a], __float_as_uint(posm[i]));
                atomicMin(&g_negBits[a], __float_as_uint(negm[i]));
            }
        }
    }
}

// ---- K5: finalize --------------------------------------------------------
__global__ void k5_finalize(float* __restrict__ out) {
    int n = g_aCnt;
    int tid = threadIdx.x;
    float sum = 0.f, cnt = 0.f;
    for (int i = tid; i < n; i += blockDim.x) {
        unsigned pb = g_posBits[i];
        unsigned nb = g_negBits[i];
        if (pb < INFBITS && nb < INFBITS) {
            float tl = fmaxf(sqrtf(__uint_as_float(pb)) -
                             sqrtf(__uint_as_float(nb)) + 0.3f, 0.f);
            sum += tl;
            cnt += 1.f;
        }
    }
    __shared__ float rs[8], rc[8];
    #pragma unroll
    for (int o = 16; o; o >>= 1) {
        sum += __shfl_xor_sync(0xffffffffu, sum, o);
        cnt += __shfl_xor_sync(0xffffffffu, cnt, o);
    }
    if ((tid & 31) == 0) { rs[tid >> 5] = sum; rc[tid >> 5] = cnt; }
    __syncthreads();
    if (tid == 0) {
        float s = 0.f, c = 0.f;
        #pragma unroll
        for (int w = 0; w < 8; w++) { s += rs[w]; c += rc[w]; }
        out[0] = (c > 0.f) ? s / fmaxf(c, 1.f) : 0.f;
    }
}

// ---------------------------------------------------------------------------
extern "C" void kernel_launch(void* const* d_in, const int* in_sizes, int n_in,
                              void* d_out, int out_size) {
    const float* feat  = (const float*)d_in[0];
    const void* labels = d_in[1];
    const void* doms   = d_in[2];
    int B = in_sizes[1];
    int D = in_sizes[0] / B;

    k0_reset<<<1, 1>>>();
    k1_init_detect<<<(B + 255) / 256, 256>>>((const unsigned*)labels, B);
    k2_partition<<<(B + 255) / 256, 256>>>(labels, doms, B);
    k3_normalize<<<dim3(B, 2), 256>>>(feat, D);
    dim3 grid((B + BN - 1) / BN, (B + BM - 1) / BM);  // covers worst-case NA/NF
    k4_gemm_min<<<grid, 256>>>(D);
    k5_finalize<<<1, 256>>>((float*)d_out);
}

// round 6
// speedup vs baseline: 3.1469x; 3.1469x over previous
#include <cuda_runtime.h>
#include <stdint.h>

// ---------------------------------------------------------------------------
// TripletContrastiveLoss — tf32 mma.sync (HMMA) version.
// tcgen05 is unavailable: the bench's PTX stage targets compute_103 (no 'a'),
// so only target-portable PTX works. mma.sync.m16n8k8.tf32 compiles for any
// sm_80+ virtual arch and runs on the Blackwell legacy tensor path.
// ---------------------------------------------------------------------------

#define BMAX 8192
#define DMAX 1024
#define INFBITS 0x7f800000u

#define BM 128
#define BN 128
#define BK 32
#define ASTR 36   // smem row stride in floats; 36%32==4 -> conflict-free frags

__device__ float g_A[(size_t)BMAX * DMAX];   // normalized anchors (tf32-rounded)
__device__ float g_F[(size_t)BMAX * DMAX];   // normalized fields  (tf32-rounded)
__device__ int   g_aRow[BMAX];
__device__ int   g_fRow[BMAX];
__device__ int   g_aLab[BMAX];
__device__ int   g_fLab[BMAX];
__device__ int   g_aCnt;
__device__ int   g_fCnt;
__device__ unsigned g_posBits[BMAX];
__device__ unsigned g_negBits[BMAX];
__device__ int   g_is64;

// ---- K0: reset scalars --------------------------------------------------
__global__ void k0_reset() {
    g_aCnt = 0;
    g_fCnt = 0;
    g_is64 = 1;
}

// ---- K1: init min arrays + label dtype detection ------------------------
// int64 labels (<2^31): every odd 32-bit word is 0. int32: some odd word !=0.
__global__ void k1_init_detect(const unsigned* __restrict__ labw, int B) {
    int i = blockIdx.x * blockDim.x + threadIdx.x;
    if (i < B) {
        g_posBits[i] = INFBITS;
        g_negBits[i] = INFBITS;
        if ((i & 1) && labw[i] != 0u) g_is64 = 0;
    }
}

// ---- K2: partition into compact anchor/field lists ----------------------
__global__ void k2_partition(const void* __restrict__ labels,
                             const void* __restrict__ doms, int B) {
    int i = blockIdx.x * blockDim.x + threadIdx.x;
    if (i >= B) return;
    int is64 = g_is64;
    long long dom, lab;
    if (is64) {
        dom = ((const long long*)doms)[i];
        lab = ((const long long*)labels)[i];
    } else {
        dom = ((const int*)doms)[i];
        lab = ((const int*)labels)[i];
    }
    if (dom == 0) {
        int p = atomicAdd(&g_aCnt, 1);
        g_aRow[p] = i;
        g_aLab[p] = (int)lab;
    } else if (dom == 1) {
        int p = atomicAdd(&g_fCnt, 1);
        g_fRow[p] = i;
        g_fLab[p] = (int)lab;
    }
}

// ---- K3: normalize + gather + tf32 round (rna) ---------------------------
__global__ void k3_normalize(const float* __restrict__ feat, int D) {
    int side = blockIdx.y;
    int n = side ? g_fCnt : g_aCnt;
    int b = blockIdx.x;
    if (b >= n) return;
    int row = side ? g_fRow[b] : g_aRow[b];
    const float4* src = (const float4*)(feat + (size_t)row * D);
    uint4* dst = (uint4*)((side ? g_F : g_A) + (size_t)b * D);
    int nv = D >> 2;
    int tid = threadIdx.x;

    float s = 0.f;
    for (int t = tid; t < nv; t += blockDim.x) {
        float4 v = src[t];
        s += v.x * v.x + v.y * v.y + v.z * v.z + v.w * v.w;
    }
    __shared__ float red[8];
    #pragma unroll
    for (int o = 16; o; o >>= 1) s += __shfl_xor_sync(0xffffffffu, s, o);
    if ((tid & 31) == 0) red[tid >> 5] = s;
    __syncthreads();
    __shared__ float s_scale;
    if (tid == 0) {
        float t = 0.f;
        #pragma unroll
        for (int w = 0; w < 8; w++) t += red[w];
        s_scale = 1.f / fmaxf(sqrtf(t), 1e-12f);
    }
    __syncthreads();
    float scale = s_scale;
    for (int t = tid; t < nv; t += blockDim.x) {
        float4 v = src[t];
        uint4 o;
        asm("cvt.rna.tf32.f32 %0, %1;" : "=r"(o.x) : "f"(v.x * scale));
        asm("cvt.rna.tf32.f32 %0, %1;" : "=r"(o.y) : "f"(v.y * scale));
        asm("cvt.rna.tf32.f32 %0, %1;" : "=r"(o.z) : "f"(v.z * scale));
        asm("cvt.rna.tf32.f32 %0, %1;" : "=r"(o.w) : "f"(v.w * scale));
        dst[t] = o;
    }
}

// ---- tf32 mma.sync wrapper ------------------------------------------------
__device__ __forceinline__ void mma_tf32(float* d, const uint32_t* a,
                                         const uint32_t* b) {
    asm volatile(
        "mma.sync.aligned.m16n8k8.row.col.f32.tf32.tf32.f32 "
        "{%0,%1,%2,%3}, {%4,%5,%6,%7}, {%8,%9}, {%0,%1,%2,%3};"
        : "+f"(d[0]), "+f"(d[1]), "+f"(d[2]), "+f"(d[3])
        : "r"(a[0]), "r"(a[1]), "r"(a[2]), "r"(a[3]), "r"(b[0]), "r"(b[1]));
}

// ---- K4: HMMA tf32 GEMM + fused masked min -------------------------------
// 8 warps, warp grid 2(M)x4(N), warp tile 64x32 = 4x4 m16n8k8 atoms.
__global__ void __launch_bounds__(256, 2)
k4_mma_min(int D) {
    __shared__ float sA[BM * ASTR];       // 18 KB
    __shared__ float sB[BN * ASTR];       // 18 KB
    __shared__ int sFlab[BN];

    const int NA = g_aCnt;
    const int NF = g_fCnt;
    const int by = blockIdx.y, bx = blockIdx.x;
    if (by * BM >= NA || bx * BN >= NF) return;

    const int tid = threadIdx.x;
    const int wid = tid >> 5;
    const int lane = tid & 31;
    const int qid = lane >> 2;      // 0..7
    const int qlane = lane & 3;     // 0..3
    const int wm = (wid & 1) * 64;  // warp M offset in tile
    const int wn = (wid >> 1) * 32; // warp N offset in tile

    if (tid < BN) {
        int f = bx * BN + tid;
        sFlab[tid] = (f < NF) ? g_fLab[f] : -1;
    }

    float acc[4][4][4];
    #pragma unroll
    for (int mi = 0; mi < 4; mi++)
        #pragma unroll
        for (int ni = 0; ni < 4; ni++)
            #pragma unroll
            for (int r = 0; r < 4; r++) acc[mi][ni][r] = 0.f;

    for (int k0 = 0; k0 < D; k0 += BK) {
        __syncthreads();   // previous iteration's fragment reads done
        // cooperative load: 128 rows x 8 float4 per matrix; 4 iters/thread
        #pragma unroll
        for (int it = 0; it < 4; it++) {
            int idx = tid + (it << 8);      // 0..1023
            int m = idx >> 3;               // row 0..127
            int q = idx & 7;                // float4 col 0..7
            float4 va = make_float4(0.f, 0.f, 0.f, 0.f);
            float4 vb = va;
            int ga = by * BM + m;
            int gf = bx * BN + m;
            if (ga < NA) va = *(const float4*)&g_A[(size_t)ga * D + k0 + q * 4];
            if (gf < NF) vb = *(const float4*)&g_F[(size_t)gf * D + k0 + q * 4];
            *(float4*)&sA[m * ASTR + q * 4] = va;
            *(float4*)&sB[m * ASTR + q * 4] = vb;
        }
        __syncthreads();

        #pragma unroll
        for (int g = 0; g < 4; g++) {       // k8 steps within the chunk
            const int kb = g * 8 + qlane;
            uint32_t a[4][4], b[4][2];
            #pragma unroll
            for (int mi = 0; mi < 4; mi++) {
                int r = wm + mi * 16 + qid;
                a[mi][0] = __float_as_uint(sA[r * ASTR + kb]);
                a[mi][1] = __float_as_uint(sA[(r + 8) * ASTR + kb]);
                a[mi][2] = __float_as_uint(sA[r * ASTR + kb + 4]);
                a[mi][3] = __float_as_uint(sA[(r + 8) * ASTR + kb + 4]);
            }
            #pragma unroll
            for (int ni = 0; ni < 4; ni++) {
                int nr = wn + ni * 8 + qid;
                b[ni][0] = __float_as_uint(sB[nr * ASTR + kb]);
                b[ni][1] = __float_as_uint(sB[nr * ASTR + kb + 4]);
            }
            #pragma unroll
            for (int mi = 0; mi < 4; mi++)
                #pragma unroll
                for (int ni = 0; ni < 4; ni++)
                    mma_tf32(acc[mi][ni], a[mi], b[ni]);
        }
    }

    // --- epilogue: d^2 = max(2 - 2*dot, 0), masked min per anchor row ----
    // Thread owns rows {wm+mi*16+qid, +8}; cols {wn+ni*8+2*qlane, +1}.
    int al[4][2];
    #pragma unroll
    for (int mi = 0; mi < 4; mi++) {
        #pragma unroll
        for (int h = 0; h < 2; h++) {
            int a_ = by * BM + wm + mi * 16 + qid + h * 8;
            al[mi][h] = (a_ < NA) ? g_aLab[a_] : -2;
        }
    }
    float posm[4][2], negm[4][2];
    #pragma unroll
    for (int mi = 0; mi < 4; mi++)
        #pragma unroll
        for (int h = 0; h < 2; h++) {
            posm[mi][h] = __uint_as_float(INFBITS);
            negm[mi][h] = posm[mi][h];
        }

    #pragma unroll
    for (int mi = 0; mi < 4; mi++) {
        #pragma unroll
        for (int ni = 0; ni < 4; ni++) {
            int n0 = wn + ni * 8 + 2 * qlane;
            int fl0 = sFlab[n0];
            int fl1 = sFlab[n0 + 1];
            #pragma unroll
            for (int h = 0; h < 2; h++) {
                float d20 = fmaxf(fmaf(-2.f, acc[mi][ni][h * 2 + 0], 2.f), 0.f);
                float d21 = fmaxf(fmaf(-2.f, acc[mi][ni][h * 2 + 1], 2.f), 0.f);
                int a_l = al[mi][h];
                if (fl0 >= 0) {
                    if (fl0 == a_l) posm[mi][h] = fminf(posm[mi][h], d20);
                    else            negm[mi][h] = fminf(negm[mi][h], d20);
                }
                if (fl1 >= 0) {
                    if (fl1 == a_l) posm[mi][h] = fminf(posm[mi][h], d21);
                    else            negm[mi][h] = fminf(negm[mi][h], d21);
                }
            }
        }
    }
    // reduce across the 4 lanes of each quad (same row, different cols)
    #pragma unroll
    for (int o = 1; o < 4; o <<= 1) {
        #pragma unroll
        for (int mi = 0; mi < 4; mi++)
            #pragma unroll
            for (int h = 0; h < 2; h++) {
                posm[mi][h] = fminf(posm[mi][h],
                                    __shfl_xor_sync(0xffffffffu, posm[mi][h], o));
                negm[mi][h] = fminf(negm[mi][h],
                                    __shfl_xor_sync(0xffffffffu, negm[mi][h], o));
            }
    }
    if (qlane == 0) {
        #pragma unroll
        for (int mi = 0; mi < 4; mi++)
            #pragma unroll
            for (int h = 0; h < 2; h++) {
                int a_ = by * BM + wm + mi * 16 + qid + h * 8;
                if (a_ < NA) {
                    atomicMin(&g_posBits[a_], __float_as_uint(posm[mi][h]));
                    atomicMin(&g_negBits[a_], __float_as_uint(negm[mi][h]));
                }
            }
    }
}

// ---- K5: finalize --------------------------------------------------------
__global__ void k5_finalize(float* __restrict__ out) {
    int n = g_aCnt;
    int tid = threadIdx.x;
    float sum = 0.f, cnt = 0.f;
    for (int i = tid; i < n; i += blockDim.x) {
        unsigned pb = g_posBits[i];
        unsigned nb = g_negBits[i];
        if (pb < INFBITS && nb < INFBITS) {
            float tl = fmaxf(sqrtf(__uint_as_float(pb)) -
                             sqrtf(__uint_as_float(nb)) + 0.3f, 0.f);
            sum += tl;
            cnt += 1.f;
        }
    }
    __shared__ float rs[8], rc[8];
    #pragma unroll
    for (int o = 16; o; o >>= 1) {
        sum += __shfl_xor_sync(0xffffffffu, sum, o);
        cnt += __shfl_xor_sync(0xffffffffu, cnt, o);
    }
    if ((tid & 31) == 0) { rs[tid >> 5] = sum; rc[tid >> 5] = cnt; }
    __syncthreads();
    if (tid == 0) {
        float s = 0.f, c = 0.f;
        #pragma unroll
        for (int w = 0; w < 8; w++) { s += rs[w]; c += rc[w]; }
        out[0] = (c > 0.f) ? s / fmaxf(c, 1.f) : 0.f;
    }
}

// ---------------------------------------------------------------------------
extern "C" void kernel_launch(void* const* d_in, const int* in_sizes, int n_in,
                              void* d_out, int out_size) {
    const float* feat  = (const float*)d_in[0];
    const void* labels = d_in[1];
    const void* doms   = d_in[2];
    int B = in_sizes[1];
    int D = in_sizes[0] / B;

    k0_reset<<<1, 1>>>();
    k1_init_detect<<<(B + 255) / 256, 256>>>((const unsigned*)labels, B);
    k2_partition<<<(B + 255) / 256, 256>>>(labels, doms, B);
    k3_normalize<<<dim3(B, 2), 256>>>(feat, D);
    dim3 grid((B + BN - 1) / BN, (B + BM - 1) / BM);  // worst-case NA/NF
    k4_mma_min<<<grid, 256>>>(D);
    k5_finalize<<<1, 256>>>((float*)d_out);
}